// round 11
// baseline (speedup 1.0000x reference)
#include <cuda_runtime.h>
#include <cuda_bf16.h>

#define N_COLS   4096
#define N_TERMS  2048
#define COL4     1024              // float4 columns
#define ROW_BLOCKS 128
#define ROWS_PER   16
#define K2_BLOCKS  16              // 16 blocks x 256 threads = 4096 columns

// ---- scratch (device globals; no allocation allowed) ----
__device__ float  g_partial[ROW_BLOCKS * N_COLS];   // 2 MB partial |x| column sums
__device__ float4 g_scale4[COL4];                   // per-column generator scale
__device__ float4 g_val4[COL4];                     // per-column delta*0.5*crossf
__device__ int4   g_cross4[COL4];                   // per-column crossing flag
__device__ int4   g_rank4[COL4];                    // per-column local rank in 256-col slice
__device__ int    g_bcount[K2_BLOCKS];              // crossings per 256-col slice

// K1 (segregated, at LTS cap): y<128 -> |x| partial column sums;
// y>=128 -> zero tail rows 2048..6143 with evict-streaming stores.
__global__ __launch_bounds__(256) void k1_reduce_zero(const float* __restrict__ x,
                                                      float* __restrict__ out) {
    int col4 = blockIdx.x * blockDim.x + threadIdx.x;   // 0..1023
    int cy   = blockIdx.y;                              // 0..383

    if (cy < ROW_BLOCKS) {
        const float4* x4 = (const float4*)x;
        int r0 = 1 + cy * ROWS_PER;
        float4 acc = make_float4(0.f, 0.f, 0.f, 0.f);
        #pragma unroll
        for (int r = 0; r < ROWS_PER; r++) {
            int row = r0 + r;
            if (row < N_TERMS) {
                float4 v = x4[(size_t)row * COL4 + col4];
                acc.x += fabsf(v.x);
                acc.y += fabsf(v.y);
                acc.z += fabsf(v.z);
                acc.w += fabsf(v.w);
            }
        }
        ((float4*)&g_partial[cy * N_COLS])[col4] = acc;
    } else {
        float4* o4 = (float4*)out;
        int r0 = N_TERMS + (cy - ROW_BLOCKS) * ROWS_PER;
        const float4 z = make_float4(0.f, 0.f, 0.f, 0.f);
        #pragma unroll
        for (int r = 0; r < ROWS_PER; r++)
            __stcs(&o4[(size_t)(r0 + r) * COL4 + col4], z);
    }
}

// K2 (PDL secondary): per-column stats + center row + block-local scan.
__global__ __launch_bounds__(256) void k2_stats(const float* __restrict__ x,
                                                float* __restrict__ out) {
    __shared__ int s_wsum[8];
    int t   = threadIdx.x;                  // 0..255
    int b   = blockIdx.x;                   // 0..15
    int col = b * 256 + t;
    int lane = t & 31, wid = t >> 5;        // 8 warps

    cudaGridDependencySynchronize();        // wait for K1's g_partial writes

    float s = 0.f;
    #pragma unroll 16
    for (int rb = 0; rb < ROW_BLOCKS; rb++)
        s += g_partial[rb * N_COLS + col];

    float c     = x[col];                   // x[0] center row
    float upper = c + s;
    float lower = c - s;
    bool  cross = (lower * upper) < 0.f;
    bool  pos   = lower >= 0.f;
    float crossf = cross ? 1.f : 0.f;
    float posf   = pos   ? 1.f : 0.f;

    float denom = upper - lower;
    float ratio = (denom != 0.f) ? (upper / denom) : 0.5f;
    float lam   = posf + crossf * ratio;

    float delta  = fmaxf(-lam * lower, (1.f - lam) * upper);
    float center = (delta * 0.5f + lam * c) * crossf + c * posf;

    ((float*)g_scale4)[col] = lam * crossf + posf;
    ((float*)g_val4)[col]   = delta * 0.5f * crossf;
    ((int*)g_cross4)[col]   = cross ? 1 : 0;
    out[col] = center;

    // block-local exclusive scan of crossing flags -> rank
    int flag = cross ? 1 : 0;
    int v = flag;
    #pragma unroll
    for (int o = 1; o < 32; o <<= 1) {
        int n = __shfl_up_sync(0xffffffffu, v, o);
        if (lane >= o) v += n;
    }
    if (lane == 31) s_wsum[wid] = v;
    __syncthreads();
    if (t < 8) {
        int wv = s_wsum[t];
        #pragma unroll
        for (int o = 1; o < 8; o <<= 1) {
            int n = __shfl_up_sync(0x000000ffu, wv, o);
            if (t >= o) wv += n;
        }
        s_wsum[t] = wv;
        if (t == 7) g_bcount[b] = wv;
    }
    __syncthreads();

    int rank = (v - flag) + ((wid > 0) ? s_wsum[wid - 1] : 0);
    ((int*)g_rank4)[col] = rank;
}

// K3 (PDL secondary): y<256 -> gens 8-row tiles; y==256 -> scatter into zeroed tail.
__global__ __launch_bounds__(256) void k3_gens_scatter(const float* __restrict__ x,
                                                       float* __restrict__ out) {
    int cy = blockIdx.y;
    cudaGridDependencySynchronize();        // wait for K2's scale/val/rank/bcount

    if (cy < 256) {
        int col4 = blockIdx.x * blockDim.x + threadIdx.x;   // 0..1023
        const float4* x4 = (const float4*)x;
        float4* o4 = (float4*)out;
        float4 sc = g_scale4[col4];
        int r0 = 1 + cy * 8;
        #pragma unroll
        for (int r = 0; r < 8; r++) {
            int row = r0 + r;
            if (row < N_TERMS) {
                float4 v = x4[(size_t)row * COL4 + col4];
                v.x *= sc.x; v.y *= sc.y; v.z *= sc.z; v.w *= sc.w;
                __stcs(&o4[(size_t)row * COL4 + col4], v);
            }
        }
    } else {
        // 4 x-blocks * 256 threads = 1024 threads, 4 consecutive columns each
        int i = blockIdx.x * blockDim.x + threadIdx.x;      // 0..1023
        int4   cf  = g_cross4[i];
        int4   rk  = g_rank4[i];
        float4 val = g_val4[i];
        int blk = i >> 6;                                   // (4*i)/256
        int base = 0;
        #pragma unroll
        for (int k = 0; k < K2_BLOCKS; k++)
            base += (k < blk) ? g_bcount[k] : 0;

        int col = i * 4;
        if (cf.x) out[(size_t)(N_TERMS + base + rk.x) * N_COLS + col + 0] = val.x;
        if (cf.y) out[(size_t)(N_TERMS + base + rk.y) * N_COLS + col + 1] = val.y;
        if (cf.z) out[(size_t)(N_TERMS + base + rk.z) * N_COLS + col + 2] = val.z;
        if (cf.w) out[(size_t)(N_TERMS + base + rk.w) * N_COLS + col + 3] = val.w;
    }
}

extern "C" void kernel_launch(void* const* d_in, const int* in_sizes, int n_in,
                              void* d_out, int out_size) {
    const float* x = (const float*)d_in[0];
    float* out     = (float*)d_out;

    dim3 g1(COL4 / 256, ROW_BLOCKS + N_COLS / ROWS_PER); // (4, 384)
    k1_reduce_zero<<<g1, 256>>>(x, out);

    cudaLaunchAttribute pdl[1];
    pdl[0].id = cudaLaunchAttributeProgrammaticStreamSerialization;
    pdl[0].val.programmaticStreamSerializationAllowed = 1;

    cudaLaunchConfig_t cfg2 = {};
    cfg2.gridDim  = dim3(K2_BLOCKS, 1, 1);
    cfg2.blockDim = dim3(256, 1, 1);
    cfg2.stream   = 0;
    cfg2.attrs    = pdl;
    cfg2.numAttrs = 1;
    cudaLaunchKernelEx(&cfg2, k2_stats, x, out);

    cudaLaunchConfig_t cfg3 = {};
    cfg3.gridDim  = dim3(COL4 / 256, 257, 1);            // (4, 257)
    cfg3.blockDim = dim3(256, 1, 1);
    cfg3.stream   = 0;
    cfg3.attrs    = pdl;
    cfg3.numAttrs = 1;
    cudaLaunchKernelEx(&cfg3, k3_gens_scatter, x, out);
}

// round 12
// speedup vs baseline: 1.5047x; 1.5047x over previous
#include <cuda_runtime.h>
#include <cuda_bf16.h>

#define N_COLS   4096
#define N_TERMS  2048
#define COL4     1024              // float4 columns
#define ROW_BLOCKS 128
#define ROWS_PER   16
#define K2_BLOCKS  64              // 64 blocks x 64 columns = 4096 columns

// ---- scratch (device globals; no allocation allowed) ----
__device__ float  g_partial[ROW_BLOCKS * N_COLS];   // 2 MB partial |x| column sums
__device__ float4 g_scale4[COL4];                   // per-column generator scale
__device__ float4 g_val4[COL4];                     // per-column delta*0.5*crossf
__device__ int4   g_cross4[COL4];                   // per-column crossing flag
__device__ int4   g_rank4[COL4];                    // per-column local rank in 64-col slice
__device__ int    g_bcount[K2_BLOCKS];              // crossings per 64-col slice

// K1 (segregated, at LTS cap): y<128 -> |x| partial column sums;
// y>=128 -> zero tail rows 2048..6143 with evict-streaming stores.
__global__ __launch_bounds__(256) void k1_reduce_zero(const float* __restrict__ x,
                                                      float* __restrict__ out) {
    int col4 = blockIdx.x * blockDim.x + threadIdx.x;   // 0..1023
    int cy   = blockIdx.y;                              // 0..383

    if (cy < ROW_BLOCKS) {
        const float4* x4 = (const float4*)x;
        int r0 = 1 + cy * ROWS_PER;
        float4 acc = make_float4(0.f, 0.f, 0.f, 0.f);
        #pragma unroll
        for (int r = 0; r < ROWS_PER; r++) {
            int row = r0 + r;
            if (row < N_TERMS) {
                float4 v = x4[(size_t)row * COL4 + col4];
                acc.x += fabsf(v.x);
                acc.y += fabsf(v.y);
                acc.z += fabsf(v.z);
                acc.w += fabsf(v.w);
            }
        }
        ((float4*)&g_partial[cy * N_COLS])[col4] = acc;
    } else {
        float4* o4 = (float4*)out;
        int r0 = N_TERMS + (cy - ROW_BLOCKS) * ROWS_PER;
        const float4 z = make_float4(0.f, 0.f, 0.f, 0.f);
        #pragma unroll
        for (int r = 0; r < ROWS_PER; r++)
            __stcs(&o4[(size_t)(r0 + r) * COL4 + col4], z);
    }
}

// K2: 64 blocks x 256 threads. 4 threads cooperatively sum one column's 128
// partials (32 each, shfl_xor combine); threads 0..63 then compute stats and
// a 64-flag scan for their 64-column slice.
__global__ __launch_bounds__(256) void k2_stats(const float* __restrict__ x,
                                                float* __restrict__ out) {
    __shared__ float s_sum[64];
    __shared__ int   s_wtot[2];
    int t = threadIdx.x;                    // 0..255
    int b = blockIdx.x;                     // 0..63

    // ---- 4-way split partial-sum per column ----
    {
        int c   = t >> 2;                   // 0..63 (column within slice)
        int p   = t & 3;                    // 0..3  (partial quarter)
        int col = b * 64 + c;
        float s = 0.f;
        int rb0 = p * 32;
        #pragma unroll 8
        for (int rb = rb0; rb < rb0 + 32; rb++)
            s += g_partial[rb * N_COLS + col];
        s += __shfl_xor_sync(0xffffffffu, s, 1);
        s += __shfl_xor_sync(0xffffffffu, s, 2);
        if (p == 0) s_sum[c] = s;
    }
    __syncthreads();

    // ---- stats + scan on threads 0..63 ----
    int lane = t & 31, w = t >> 5;
    int flag = 0;
    int col  = b * 64 + t;
    float scale = 0.f, val = 0.f, center = 0.f;
    if (t < 64) {
        float s     = s_sum[t];
        float c     = x[col];               // x[0] center row
        float upper = c + s;
        float lower = c - s;
        bool  cross = (lower * upper) < 0.f;
        bool  pos   = lower >= 0.f;
        float crossf = cross ? 1.f : 0.f;
        float posf   = pos   ? 1.f : 0.f;

        float denom = upper - lower;
        float ratio = (denom != 0.f) ? (upper / denom) : 0.5f;
        float lam   = posf + crossf * ratio;

        float delta = fmaxf(-lam * lower, (1.f - lam) * upper);
        center = (delta * 0.5f + lam * c) * crossf + c * posf;
        scale  = lam * crossf + posf;
        val    = delta * 0.5f * crossf;
        flag   = cross ? 1 : 0;
    }

    // inclusive warp scan of flags (warps 0,1 carry data; others idle-safe)
    int v = flag;
    #pragma unroll
    for (int o = 1; o < 32; o <<= 1) {
        int n = __shfl_up_sync(0xffffffffu, v, o);
        if (lane >= o) v += n;
    }
    if (t < 64 && lane == 31) s_wtot[w] = v;
    __syncthreads();

    if (t < 64) {
        ((float*)g_scale4)[col] = scale;
        ((float*)g_val4)[col]   = val;
        ((int*)g_cross4)[col]   = flag;
        out[col] = center;

        int rank = (v - flag) + ((w == 1) ? s_wtot[0] : 0);
        ((int*)g_rank4)[col] = rank;
        if (t == 63) g_bcount[b] = s_wtot[0] + s_wtot[1];
    }
}

// K3: y<256 -> gens 8-row tiles (rows 1..2047); y==256 -> scatter into zeroed tail.
__global__ __launch_bounds__(256) void k3_gens_scatter(const float* __restrict__ x,
                                                       float* __restrict__ out) {
    int cy = blockIdx.y;
    if (cy < 256) {
        int col4 = blockIdx.x * blockDim.x + threadIdx.x;   // 0..1023
        const float4* x4 = (const float4*)x;
        float4* o4 = (float4*)out;
        float4 sc = g_scale4[col4];
        int r0 = 1 + cy * 8;
        #pragma unroll
        for (int r = 0; r < 8; r++) {
            int row = r0 + r;
            if (row < N_TERMS) {
                float4 v = x4[(size_t)row * COL4 + col4];
                v.x *= sc.x; v.y *= sc.y; v.z *= sc.z; v.w *= sc.w;
                __stcs(&o4[(size_t)row * COL4 + col4], v);
            }
        }
    } else {
        // 4 x-blocks * 256 threads = 1024 threads, 4 consecutive columns each.
        // 4 consecutive cols never straddle a 64-col slice (col = 4i, 4i%64 <= 60).
        int i = blockIdx.x * blockDim.x + threadIdx.x;      // 0..1023
        int4   cf  = g_cross4[i];
        int4   rk  = g_rank4[i];
        float4 val = g_val4[i];
        int blk = i >> 4;                                   // (4*i)/64
        int base = 0;
        #pragma unroll
        for (int k = 0; k < K2_BLOCKS; k++)
            base += (k < blk) ? g_bcount[k] : 0;

        int col = i * 4;
        if (cf.x) out[(size_t)(N_TERMS + base + rk.x) * N_COLS + col + 0] = val.x;
        if (cf.y) out[(size_t)(N_TERMS + base + rk.y) * N_COLS + col + 1] = val.y;
        if (cf.z) out[(size_t)(N_TERMS + base + rk.z) * N_COLS + col + 2] = val.z;
        if (cf.w) out[(size_t)(N_TERMS + base + rk.w) * N_COLS + col + 3] = val.w;
    }
}

extern "C" void kernel_launch(void* const* d_in, const int* in_sizes, int n_in,
                              void* d_out, int out_size) {
    const float* x = (const float*)d_in[0];
    float* out     = (float*)d_out;

    dim3 g1(COL4 / 256, ROW_BLOCKS + N_COLS / ROWS_PER); // (4, 384)
    k1_reduce_zero<<<g1, 256>>>(x, out);
    k2_stats<<<K2_BLOCKS, 256>>>(x, out);
    dim3 g3(COL4 / 256, 257);                            // (4, 257)
    k3_gens_scatter<<<g3, 256>>>(x, out);
}